// round 1
// baseline (speedup 1.0000x reference)
#include <cuda_runtime.h>
#include <cstdint>
#include <cstddef>

#define BATCH 128
#define SEQ   1024
#define DIN   512
#define HID   512

// xp[s][b][h] scratch: 1024*128*512 fp32 = 256MB (device global — allocation-free)
__device__ float g_xp[SEQ * BATCH * HID];

// ---------------- f32x2 packed-math helpers ----------------
static __device__ __forceinline__ unsigned long long dup2(float a) {
    unsigned long long r;
    asm("mov.b64 %0, {%1, %1};" : "=l"(r) : "f"(a));
    return r;
}
static __device__ __forceinline__ unsigned long long pack2(float a, float b) {
    unsigned long long r;
    asm("mov.b64 %0, {%1, %2};" : "=l"(r) : "f"(a), "f"(b));
    return r;
}
static __device__ __forceinline__ void unpack2(unsigned long long v, float& lo, float& hi) {
    asm("mov.b64 {%0, %1}, %2;" : "=f"(lo), "=f"(hi) : "l"(v));
}
static __device__ __forceinline__ void fma2(unsigned long long& acc,
                                            unsigned long long a,
                                            unsigned long long b) {
    asm("fma.rn.f32x2 %0, %1, %2, %0;" : "+l"(acc) : "l"(a), "l"(b));
}

// ============================================================
// Kernel A: xp[s][b][j] = sum_d x[b][s][d]*Wx[d][j] + bias[j]
// 128x128 tile, BK=16, double-buffered smem, FFMA2 micro-kernel
// ============================================================
__global__ void __launch_bounds__(256, 2) xp_gemm(
    const float* __restrict__ x,
    const float* __restrict__ Wx,
    const float* __restrict__ bias)
{
    __shared__ __align__(16) float xs[2][16][128];   // transposed: [k][token]
    __shared__ __align__(16) float ws[2][16][132];   // [k][j], padded

    const int tid = threadIdx.x;
    const int tx = tid & 15, ty = tid >> 4;
    const int jn0 = blockIdx.x * 128;          // N-tile (0..3)
    const int mt  = blockIdx.y;                // M-tile (0..1023)
    const int bb  = mt >> 3;                   // batch
    const int s0  = (mt & 7) * 128;            // seq offset

    const float* xbase = x + ((size_t)bb * SEQ + s0) * DIN;
    const int la_tok = tid >> 2, la_kv = tid & 3;   // x loader
    const int lb_row = tid >> 5, lb_jv = tid & 31;  // w loader

    unsigned long long acc[4][8];
#pragma unroll
    for (int p = 0; p < 4; p++)
#pragma unroll
        for (int q = 0; q < 8; q++) acc[p][q] = 0ULL;

    // prologue: chunk 0
    {
        float4 ra0 = *(const float4*)(xbase + (size_t)la_tok * DIN + la_kv * 4);
        float4 ra1 = *(const float4*)(xbase + (size_t)(la_tok + 64) * DIN + la_kv * 4);
        float4 rb0 = *(const float4*)(Wx + (size_t)lb_row * HID + jn0 + lb_jv * 4);
        float4 rb1 = *(const float4*)(Wx + (size_t)(lb_row + 8) * HID + jn0 + lb_jv * 4);
        xs[0][la_kv*4+0][la_tok]=ra0.x; xs[0][la_kv*4+1][la_tok]=ra0.y;
        xs[0][la_kv*4+2][la_tok]=ra0.z; xs[0][la_kv*4+3][la_tok]=ra0.w;
        xs[0][la_kv*4+0][la_tok+64]=ra1.x; xs[0][la_kv*4+1][la_tok+64]=ra1.y;
        xs[0][la_kv*4+2][la_tok+64]=ra1.z; xs[0][la_kv*4+3][la_tok+64]=ra1.w;
        *(float4*)&ws[0][lb_row][lb_jv*4]   = rb0;
        *(float4*)&ws[0][lb_row+8][lb_jv*4] = rb1;
    }
    __syncthreads();

    int buf = 0;
    for (int kc = 0; kc < 32; kc++) {
        float4 ra0, ra1, rb0, rb1;
        const bool pf = (kc + 1) < 32;
        if (pf) {
            const int k0 = (kc + 1) * 16;
            ra0 = *(const float4*)(xbase + (size_t)la_tok * DIN + k0 + la_kv * 4);
            ra1 = *(const float4*)(xbase + (size_t)(la_tok + 64) * DIN + k0 + la_kv * 4);
            rb0 = *(const float4*)(Wx + (size_t)(k0 + lb_row) * HID + jn0 + lb_jv * 4);
            rb1 = *(const float4*)(Wx + (size_t)(k0 + lb_row + 8) * HID + jn0 + lb_jv * 4);
        }
#pragma unroll
        for (int kk = 0; kk < 16; kk++) {
            const double2 xa = *(const double2*)&xs[buf][kk][ty * 8];
            const double2 xb = *(const double2*)&xs[buf][kk][ty * 8 + 4];
            const float4 w0 = *(const float4*)&ws[buf][kk][tx * 8];
            const float4 w1 = *(const float4*)&ws[buf][kk][tx * 8 + 4];
            unsigned long long xr[4];
            xr[0] = __double_as_longlong(xa.x);
            xr[1] = __double_as_longlong(xa.y);
            xr[2] = __double_as_longlong(xb.x);
            xr[3] = __double_as_longlong(xb.y);
            unsigned long long wd[8];
            wd[0]=dup2(w0.x); wd[1]=dup2(w0.y); wd[2]=dup2(w0.z); wd[3]=dup2(w0.w);
            wd[4]=dup2(w1.x); wd[5]=dup2(w1.y); wd[6]=dup2(w1.z); wd[7]=dup2(w1.w);
#pragma unroll
            for (int p = 0; p < 4; p++)
#pragma unroll
                for (int q = 0; q < 8; q++)
                    fma2(acc[p][q], xr[p], wd[q]);
        }
        if (pf) {
            const int nb = buf ^ 1;
            xs[nb][la_kv*4+0][la_tok]=ra0.x; xs[nb][la_kv*4+1][la_tok]=ra0.y;
            xs[nb][la_kv*4+2][la_tok]=ra0.z; xs[nb][la_kv*4+3][la_tok]=ra0.w;
            xs[nb][la_kv*4+0][la_tok+64]=ra1.x; xs[nb][la_kv*4+1][la_tok+64]=ra1.y;
            xs[nb][la_kv*4+2][la_tok+64]=ra1.z; xs[nb][la_kv*4+3][la_tok+64]=ra1.w;
            *(float4*)&ws[nb][lb_row][lb_jv*4]   = rb0;
            *(float4*)&ws[nb][lb_row+8][lb_jv*4] = rb1;
        }
        __syncthreads();
        buf ^= 1;
    }

    // epilogue: add bias, write xp[s][b][j]
    const float4 bv0 = *(const float4*)&bias[jn0 + tx * 8];
    const float4 bv1 = *(const float4*)&bias[jn0 + tx * 8 + 4];
#pragma unroll
    for (int p = 0; p < 4; p++) {
        float lo[8], hi[8];
#pragma unroll
        for (int q = 0; q < 8; q++) unpack2(acc[p][q], lo[q], hi[q]);
        const int r0 = ty * 8 + 2 * p;
        float* o0 = g_xp + ((size_t)(s0 + r0) * BATCH + bb) * HID + jn0 + tx * 8;
        float* o1 = o0 + (size_t)BATCH * HID;   // next s row
        float4 v;
        v.x=lo[0]+bv0.x; v.y=lo[1]+bv0.y; v.z=lo[2]+bv0.z; v.w=lo[3]+bv0.w; *(float4*)o0 = v;
        v.x=lo[4]+bv1.x; v.y=lo[5]+bv1.y; v.z=lo[6]+bv1.z; v.w=lo[7]+bv1.w; *(float4*)(o0+4) = v;
        v.x=hi[0]+bv0.x; v.y=hi[1]+bv0.y; v.z=hi[2]+bv0.z; v.w=hi[3]+bv0.w; *(float4*)o1 = v;
        v.x=hi[4]+bv1.x; v.y=hi[5]+bv1.y; v.z=hi[6]+bv1.z; v.w=hi[7]+bv1.w; *(float4*)(o1+4) = v;
    }
}

// ============================================================
// Kernel B: persistent cluster scan
// 16 clusters x 8 CTAs. CTA rank r holds Wh[:, r*64:(r+1)*64] in smem (128KB).
// h (8 rows x 512) replicated per CTA, double-buffered; per-step each CTA
// computes its 64 output columns for 8 batch rows, tanh, then broadcasts the
// slice to all 8 peer CTAs via DSMEM; one cluster barrier per step.
// ============================================================
#define SMEM_SCAN (512*64*4 + 2*512*8*4 + 4*4*64*8)   // Whs + hbuf + red = 172032

__global__ void __launch_bounds__(256, 1) __cluster_dims__(8, 1, 1)
rnn_scan(const float* __restrict__ Wh, float* __restrict__ out)
{
    extern __shared__ __align__(16) float smem[];
    float* Whs  = smem;                        // [512][64]   (k-major, local cols)
    float* hbuf = smem + 512 * 64;             // [2][512][8] (k-major, 8 batch rows)
    unsigned long long* red =
        (unsigned long long*)(hbuf + 2 * 512 * 8);   // [(s*4+p)*64 + c] f32x2 partials

    const int tid  = threadIdx.x;
    const int rank = blockIdx.x & 7;           // cluster rank (cluster dims 8x1x1)
    const int cid  = blockIdx.x >> 3;          // cluster id (0..15)
    const int sk   = tid >> 6;                 // k-slice (compute) / row-pair p (reduce)
    const int c    = tid & 63;                 // local column
    const int jg   = rank * 64 + c;            // global hidden index
    const int b0   = cid * 8 + 2 * sk;         // batch rows 2sk, 2sk+1 of this cluster

    // load Wh slice: Wh[k][rank*64 .. +63] -> Whs[k][0..63]
    for (int i = tid; i < 512 * 16; i += 256) {
        const int k = i >> 4, jv = i & 15;
        *(float4*)&Whs[k * 64 + jv * 4] =
            *(const float4*)&Wh[(size_t)k * HID + rank * 64 + jv * 4];
    }
    // h0 = 0
    for (int i = tid; i < 2 * 512 * 8; i += 256) hbuf[i] = 0.0f;

    uint32_t hbuf_u32;
    asm("{ .reg .u64 t; cvta.to.shared.u64 t, %1; cvt.u32.u64 %0, t; }"
        : "=r"(hbuf_u32) : "l"(hbuf));

    asm volatile("barrier.cluster.arrive.aligned;" ::: "memory");
    asm volatile("barrier.cluster.wait.aligned;"   ::: "memory");

    const float* whp = Whs + (sk * 128) * 64 + c;   // this thread's k-slice column

    for (int t = 0; t < SEQ; t++) {
        const int cur = t & 1, nxt = cur ^ 1;

        // prefetch xp early (hidden behind the k-loop)
        const float* xpt = g_xp + (size_t)t * (BATCH * HID);
        const float xp0 = xpt[(size_t)b0 * HID + jg];
        const float xp1 = xpt[(size_t)(b0 + 1) * HID + jg];

        const unsigned long long* hc =
            (const unsigned long long*)(hbuf + cur * (512 * 8)) + (size_t)sk * 128 * 4;
        unsigned long long a0 = 0, a1 = 0, a2 = 0, a3 = 0;
#pragma unroll 8
        for (int kk = 0; kk < 128; kk++) {
            const unsigned long long wd = dup2(whp[kk * 64]);      // LDS.32 + dup
            const ulonglong2 h01 = *(const ulonglong2*)(hc + kk * 4);     // LDS.128 (bcast)
            const ulonglong2 h23 = *(const ulonglong2*)(hc + kk * 4 + 2); // LDS.128 (bcast)
            fma2(a0, h01.x, wd);
            fma2(a1, h01.y, wd);
            fma2(a2, h23.x, wd);
            fma2(a3, h23.y, wd);
        }
        // k-slice partials -> smem
        red[((sk << 2) + 0) * 64 + c] = a0;
        red[((sk << 2) + 1) * 64 + c] = a1;
        red[((sk << 2) + 2) * 64 + c] = a2;
        red[((sk << 2) + 3) * 64 + c] = a3;
        __syncthreads();

        // reduce 4 k-slices for row-pair p=sk, column c
        float s0f = 0.f, s1f = 0.f;
#pragma unroll
        for (int ss = 0; ss < 4; ss++) {
            float lo, hi;
            unpack2(red[((ss << 2) + sk) * 64 + c], lo, hi);
            s0f += lo; s1f += hi;
        }
        const float v0 = tanhf(s0f + xp0);
        const float v1 = tanhf(s1f + xp1);
        const unsigned long long hv = pack2(v0, v1);

        // broadcast our slice element to hbuf[nxt] of all 8 cluster CTAs
        const uint32_t laddr =
            hbuf_u32 + (uint32_t)(((nxt * 512 + jg) * 8 + 2 * sk) * 4);
#pragma unroll
        for (int r = 0; r < 8; r++) {
            uint32_t rem;
            asm volatile("mapa.shared::cluster.u32 %0, %1, %2;"
                         : "=r"(rem) : "r"(laddr), "r"(r));
            asm volatile("st.shared::cluster.b64 [%0], %1;"
                         :: "r"(rem), "l"(hv) : "memory");
        }
        asm volatile("barrier.cluster.arrive.aligned;" ::: "memory");
        asm volatile("barrier.cluster.wait.aligned;"   ::: "memory");
    }

    // final h lives in hbuf[0] (t=1023 wrote buffer (1023+1)&1 = 0)
    out[(size_t)b0 * HID + jg]       = hbuf[jg * 8 + 2 * sk];
    out[(size_t)(b0 + 1) * HID + jg] = hbuf[jg * 8 + 2 * sk + 1];
}

// ============================================================
extern "C" void kernel_launch(void* const* d_in, const int* in_sizes, int n_in,
                              void* d_out, int out_size)
{
    (void)in_sizes; (void)n_in; (void)out_size;
    const float* x    = (const float*)d_in[0];
    const float* Wx   = (const float*)d_in[1];
    const float* Wh   = (const float*)d_in[2];
    const float* bias = (const float*)d_in[3];
    float* out = (float*)d_out;

    cudaFuncSetAttribute(rnn_scan, cudaFuncAttributeMaxDynamicSharedMemorySize, SMEM_SCAN);

    dim3 g1(4, 1024);   // 4 N-tiles x (128 batches * 8 seq-blocks)
    xp_gemm<<<g1, 256>>>(x, Wx, bias);
    rnn_scan<<<128, 256, SMEM_SCAN>>>(Wh, out);
}

// round 2
// speedup vs baseline: 1.4067x; 1.4067x over previous
#include <cuda_runtime.h>
#include <cstdint>
#include <cstddef>

#define BATCH 128
#define SEQ   1024
#define DIN   512
#define HID   512

// xp[s][b][h] scratch: 1024*128*512 fp32 = 256MB (device global — allocation-free)
__device__ float g_xp[SEQ * BATCH * HID];

// ---------------- f32x2 packed-math helpers ----------------
typedef unsigned long long ull;
static __device__ __forceinline__ ull dup2(float a) {
    ull r; asm("mov.b64 %0, {%1, %1};" : "=l"(r) : "f"(a)); return r;
}
static __device__ __forceinline__ ull pack2(float a, float b) {
    ull r; asm("mov.b64 %0, {%1, %2};" : "=l"(r) : "f"(a), "f"(b)); return r;
}
static __device__ __forceinline__ void unpack2(ull v, float& lo, float& hi) {
    asm("mov.b64 {%0, %1}, %2;" : "=f"(lo), "=f"(hi) : "l"(v));
}
static __device__ __forceinline__ void fma2(ull& acc, ull a, ull b) {
    asm("fma.rn.f32x2 %0, %1, %2, %0;" : "+l"(acc) : "l"(a), "l"(b));
}
static __device__ __forceinline__ void add2(ull& acc, ull b) {
    asm("add.rn.f32x2 %0, %0, %1;" : "+l"(acc) : "l"(b));
}

// ============================================================
// Kernel A: xp[s][b][j] = sum_d x[b][s][d]*Wx[d][j] + bias[j]
// (unchanged from R1 — ~1.3ms, FFMA2 SGEMM)
// ============================================================
__global__ void __launch_bounds__(256, 2) xp_gemm(
    const float* __restrict__ x,
    const float* __restrict__ Wx,
    const float* __restrict__ bias)
{
    __shared__ __align__(16) float xs[2][16][128];
    __shared__ __align__(16) float ws[2][16][132];

    const int tid = threadIdx.x;
    const int tx = tid & 15, ty = tid >> 4;
    const int jn0 = blockIdx.x * 128;
    const int mt  = blockIdx.y;
    const int bb  = mt >> 3;
    const int s0  = (mt & 7) * 128;

    const float* xbase = x + ((size_t)bb * SEQ + s0) * DIN;
    const int la_tok = tid >> 2, la_kv = tid & 3;
    const int lb_row = tid >> 5, lb_jv = tid & 31;

    ull acc[4][8];
#pragma unroll
    for (int p = 0; p < 4; p++)
#pragma unroll
        for (int q = 0; q < 8; q++) acc[p][q] = 0ULL;

    {
        float4 ra0 = *(const float4*)(xbase + (size_t)la_tok * DIN + la_kv * 4);
        float4 ra1 = *(const float4*)(xbase + (size_t)(la_tok + 64) * DIN + la_kv * 4);
        float4 rb0 = *(const float4*)(Wx + (size_t)lb_row * HID + jn0 + lb_jv * 4);
        float4 rb1 = *(const float4*)(Wx + (size_t)(lb_row + 8) * HID + jn0 + lb_jv * 4);
        xs[0][la_kv*4+0][la_tok]=ra0.x; xs[0][la_kv*4+1][la_tok]=ra0.y;
        xs[0][la_kv*4+2][la_tok]=ra0.z; xs[0][la_kv*4+3][la_tok]=ra0.w;
        xs[0][la_kv*4+0][la_tok+64]=ra1.x; xs[0][la_kv*4+1][la_tok+64]=ra1.y;
        xs[0][la_kv*4+2][la_tok+64]=ra1.z; xs[0][la_kv*4+3][la_tok+64]=ra1.w;
        *(float4*)&ws[0][lb_row][lb_jv*4]   = rb0;
        *(float4*)&ws[0][lb_row+8][lb_jv*4] = rb1;
    }
    __syncthreads();

    int buf = 0;
    for (int kc = 0; kc < 32; kc++) {
        float4 ra0, ra1, rb0, rb1;
        const bool pf = (kc + 1) < 32;
        if (pf) {
            const int k0 = (kc + 1) * 16;
            ra0 = *(const float4*)(xbase + (size_t)la_tok * DIN + k0 + la_kv * 4);
            ra1 = *(const float4*)(xbase + (size_t)(la_tok + 64) * DIN + k0 + la_kv * 4);
            rb0 = *(const float4*)(Wx + (size_t)(k0 + lb_row) * HID + jn0 + lb_jv * 4);
            rb1 = *(const float4*)(Wx + (size_t)(k0 + lb_row + 8) * HID + jn0 + lb_jv * 4);
        }
#pragma unroll
        for (int kk = 0; kk < 16; kk++) {
            const double2 xa = *(const double2*)&xs[buf][kk][ty * 8];
            const double2 xb = *(const double2*)&xs[buf][kk][ty * 8 + 4];
            const float4 w0 = *(const float4*)&ws[buf][kk][tx * 8];
            const float4 w1 = *(const float4*)&ws[buf][kk][tx * 8 + 4];
            ull xr[4];
            xr[0] = __double_as_longlong(xa.x);
            xr[1] = __double_as_longlong(xa.y);
            xr[2] = __double_as_longlong(xb.x);
            xr[3] = __double_as_longlong(xb.y);
            ull wd[8];
            wd[0]=dup2(w0.x); wd[1]=dup2(w0.y); wd[2]=dup2(w0.z); wd[3]=dup2(w0.w);
            wd[4]=dup2(w1.x); wd[5]=dup2(w1.y); wd[6]=dup2(w1.z); wd[7]=dup2(w1.w);
#pragma unroll
            for (int p = 0; p < 4; p++)
#pragma unroll
                for (int q = 0; q < 8; q++)
                    fma2(acc[p][q], xr[p], wd[q]);
        }
        if (pf) {
            const int nb = buf ^ 1;
            xs[nb][la_kv*4+0][la_tok]=ra0.x; xs[nb][la_kv*4+1][la_tok]=ra0.y;
            xs[nb][la_kv*4+2][la_tok]=ra0.z; xs[nb][la_kv*4+3][la_tok]=ra0.w;
            xs[nb][la_kv*4+0][la_tok+64]=ra1.x; xs[nb][la_kv*4+1][la_tok+64]=ra1.y;
            xs[nb][la_kv*4+2][la_tok+64]=ra1.z; xs[nb][la_kv*4+3][la_tok+64]=ra1.w;
            *(float4*)&ws[nb][lb_row][lb_jv*4]   = rb0;
            *(float4*)&ws[nb][lb_row+8][lb_jv*4] = rb1;
        }
        __syncthreads();
        buf ^= 1;
    }

    const float4 bv0 = *(const float4*)&bias[jn0 + tx * 8];
    const float4 bv1 = *(const float4*)&bias[jn0 + tx * 8 + 4];
#pragma unroll
    for (int p = 0; p < 4; p++) {
        float lo[8], hi[8];
#pragma unroll
        for (int q = 0; q < 8; q++) unpack2(acc[p][q], lo[q], hi[q]);
        const int r0 = ty * 8 + 2 * p;
        float* o0 = g_xp + ((size_t)(s0 + r0) * BATCH + bb) * HID + jn0 + tx * 8;
        float* o1 = o0 + (size_t)BATCH * HID;
        float4 v;
        v.x=lo[0]+bv0.x; v.y=lo[1]+bv0.y; v.z=lo[2]+bv0.z; v.w=lo[3]+bv0.w; *(float4*)o0 = v;
        v.x=lo[4]+bv1.x; v.y=lo[5]+bv1.y; v.z=lo[6]+bv1.z; v.w=lo[7]+bv1.w; *(float4*)(o0+4) = v;
        v.x=hi[0]+bv0.x; v.y=hi[1]+bv0.y; v.z=hi[2]+bv0.z; v.w=hi[3]+bv0.w; *(float4*)o1 = v;
        v.x=hi[4]+bv1.x; v.y=hi[5]+bv1.y; v.z=hi[6]+bv1.z; v.w=hi[7]+bv1.w; *(float4*)(o1+4) = v;
    }
}

// ============================================================
// Kernel B: persistent cluster scan, v2
//  - 512 threads/CTA, 16 k-slices x 32 col-pairs
//  - staged 16B DSMEM broadcast (precomputed mapa)
//  - mbarrier arrive/wait instead of cluster.sync per step
// ============================================================
#define WHS_FLOATS  (512 * 64)          // 128KB
#define HBUF_FLOATS (2 * 512 * 8)       // 32KB : hbuf[buf][k][row]
#define RED_ULL     (16 * 4 * 64)       // 32KB : red[(ksl*4+rp)*64 + col]
#define SMEM_SCAN2  ((WHS_FLOATS + HBUF_FLOATS) * 4 + RED_ULL * 8 + 16)

static __device__ __forceinline__ void bar_wait_cluster(uint32_t mb, uint32_t parity) {
    uint32_t done;
    asm volatile(
        "{\n\t.reg .pred p;\n\t"
        "mbarrier.try_wait.parity.acquire.cluster.shared::cta.b64 p, [%1], %2;\n\t"
        "selp.b32 %0, 1, 0, p;\n\t}"
        : "=r"(done) : "r"(mb), "r"(parity) : "memory");
    if (!done) {
        asm volatile(
            "{\n\t.reg .pred P1;\n\t"
            "W_%=:\n\t"
            "mbarrier.try_wait.parity.acquire.cluster.shared::cta.b64 P1, [%0], %1, 0x989680;\n\t"
            "@P1 bra.uni D_%=;\n\t"
            "bra.uni W_%=;\n\t"
            "D_%=:\n\t}"
            :: "r"(mb), "r"(parity) : "memory");
    }
}

__global__ void __launch_bounds__(512, 1) __cluster_dims__(8, 1, 1)
rnn_scan(const float* __restrict__ Wh, float* __restrict__ out)
{
    extern __shared__ __align__(16) float smem[];
    float* Whs  = smem;                                   // [512][64]
    float* hbuf = smem + WHS_FLOATS;                      // [2][512][8]
    ull*   red  = (ull*)(hbuf + HBUF_FLOATS);             // [16*4][64]
    ull*   mbar = red + RED_ULL;

    const int tid  = threadIdx.x;
    const int rank = blockIdx.x & 7;
    const int cid  = blockIdx.x >> 3;
    const int ksl  = tid >> 5;          // 0..15 (warp id)
    const int c2   = tid & 31;          // col-pair 0..31

    uint32_t mbar_u32, hbuf_u32;
    asm("{ .reg .u64 t; cvta.to.shared.u64 t, %1; cvt.u32.u64 %0, t; }"
        : "=r"(mbar_u32) : "l"(mbar));
    asm("{ .reg .u64 t; cvta.to.shared.u64 t, %1; cvt.u32.u64 %0, t; }"
        : "=r"(hbuf_u32) : "l"(hbuf));

    // load Wh slice: Wh[k][rank*64 + j] -> Whs[k][j]
    for (int i = tid; i < 512 * 16; i += 512) {
        const int k = i >> 4, jv = i & 15;
        *(float4*)&Whs[k * 64 + jv * 4] =
            *(const float4*)&Wh[(size_t)k * HID + rank * 64 + jv * 4];
    }
    for (int i = tid; i < HBUF_FLOATS; i += 512) hbuf[i] = 0.0f;
    if (tid == 0) {
        asm volatile("mbarrier.init.shared.b64 [%0], 8;" :: "r"(mbar_u32) : "memory");
    }

    // ---- precomputed broadcast plan (loop-invariant) ----
    // our outgoing slice = hbuf[buf] + rank*2048B, 128 chunks of 16B
    const int chunk = tid & 127;
    const int pg    = tid >> 7;                 // 0..3
    const int p1v   = pg + 4;                   // second peer (valid if pg<3)
    const int rr0   = pg  + (pg  >= rank ? 1 : 0);
    const int rr1   = p1v + (p1v >= rank ? 1 : 0);
    const uint32_t slice_addr = hbuf_u32 + (uint32_t)(rank * 2048 + chunk * 16);
    uint32_t bc0, bc1 = 0;
    asm("mapa.shared::cluster.u32 %0, %1, %2;" : "=r"(bc0) : "r"(slice_addr), "r"(rr0));
    if (pg < 3)
        asm("mapa.shared::cluster.u32 %0, %1, %2;" : "=r"(bc1) : "r"(slice_addr), "r"(rr1));
    uint32_t arr_addr = 0;
    if (tid < 8)
        asm("mapa.shared::cluster.u32 %0, %1, %2;" : "=r"(arr_addr) : "r"(mbar_u32), "r"(tid));

    // reducer / output thread mapping (tid < 256)
    const int rp = (tid >> 6) & 3;      // row-pair 0..3
    const int c  = tid & 63;            // column 0..63
    const int jg = rank * 64 + c;       // global hidden index
    const int b0 = cid * 8 + 2 * rp;    // batch rows

    asm volatile("barrier.cluster.arrive.aligned;" ::: "memory");
    asm volatile("barrier.cluster.wait.aligned;"   ::: "memory");

    const float* whbase = Whs + (ksl * 32) * 64 + 2 * c2;

    for (int t = 0; t < SEQ; t++) {
        const int cur = t & 1, nxt = cur ^ 1;

        // xp prefetch (overlaps the wait + k-loop)
        float xp0 = 0.f, xp1 = 0.f;
        if (tid < 256) {
            const float* xpt = g_xp + (size_t)t * (BATCH * HID);
            xp0 = xpt[(size_t)b0 * HID + jg];
            xp1 = xpt[(size_t)(b0 + 1) * HID + jg];
        }

        // wait for previous step's h broadcast (phase t-1)
        if (t > 0) bar_wait_cluster(mbar_u32, (uint32_t)((t - 1) & 1));

        const ull* hc = (const ull*)(hbuf + cur * 4096) + (size_t)ksl * 32 * 4;
        ull a00=0,a01=0,a10=0,a11=0,a20=0,a21=0,a30=0,a31=0;
#pragma unroll 8
        for (int kk = 0; kk < 32; kk++) {
            const ull wp = *(const ull*)(whbase + kk * 64);      // LDS.64 (2 cols)
            float w0, w1; unpack2(wp, w0, w1);
            const ull wd0 = dup2(w0), wd1 = dup2(w1);
            const ulonglong2 h01 = *(const ulonglong2*)(hc + kk * 4);       // rows 0-3
            const ulonglong2 h23 = *(const ulonglong2*)(hc + kk * 4 + 2);   // rows 4-7
            fma2(a00, h01.x, wd0); fma2(a01, h01.x, wd1);
            fma2(a10, h01.y, wd0); fma2(a11, h01.y, wd1);
            fma2(a20, h23.x, wd0); fma2(a21, h23.x, wd1);
            fma2(a30, h23.y, wd0); fma2(a31, h23.y, wd1);
        }
        {   // partials -> red, 4x STS.128
            ulonglong2 v;
            v.x=a00; v.y=a01; *(ulonglong2*)&red[(ksl*4+0)*64 + 2*c2] = v;
            v.x=a10; v.y=a11; *(ulonglong2*)&red[(ksl*4+1)*64 + 2*c2] = v;
            v.x=a20; v.y=a21; *(ulonglong2*)&red[(ksl*4+2)*64 + 2*c2] = v;
            v.x=a30; v.y=a31; *(ulonglong2*)&red[(ksl*4+3)*64 + 2*c2] = v;
        }
        __syncthreads();

        if (tid < 256) {
            ull s = red[rp * 64 + c];
#pragma unroll
            for (int ss = 1; ss < 16; ss++) add2(s, red[(ss * 4 + rp) * 64 + c]);
            float lo, hi; unpack2(s, lo, hi);
            const float v0 = tanhf(lo + xp0);
            const float v1 = tanhf(hi + xp1);
            // write own slice directly into local hbuf[nxt] (also the bcast source)
            *(ull*)&hbuf[nxt * 4096 + jg * 8 + 2 * rp] = pack2(v0, v1);
        }
        __syncthreads();

        {   // broadcast our 2KB slice to the 7 peers, 16B chunks
            const float* srcp = hbuf + nxt * 4096 + rank * 512 + chunk * 4;
            const ulonglong2 val = *(const ulonglong2*)srcp;
            const uint32_t boff = (uint32_t)(nxt * 16384);
            asm volatile("st.shared::cluster.v2.u64 [%0], {%1, %2};"
                         :: "r"(bc0 + boff), "l"(val.x), "l"(val.y) : "memory");
            if (pg < 3)
                asm volatile("st.shared::cluster.v2.u64 [%0], {%1, %2};"
                             :: "r"(bc1 + boff), "l"(val.x), "l"(val.y) : "memory");
        }
        __syncthreads();   // make all threads' remote stores visible before release-arrive

        if (tid < 8) {
            asm volatile("mbarrier.arrive.release.cluster.shared::cluster.b64 _, [%0];"
                         :: "r"(arr_addr) : "memory");
        }
    }

    // consume final phase (t=1023 -> parity 1); final h lives in hbuf[0]
    bar_wait_cluster(mbar_u32, 1u);
    if (tid < 256) {
        const float2 hv = *(const float2*)&hbuf[0 * 4096 + jg * 8 + 2 * rp];
        out[(size_t)b0 * HID + jg]       = hv.x;
        out[(size_t)(b0 + 1) * HID + jg] = hv.y;
    }

    asm volatile("barrier.cluster.arrive.aligned;" ::: "memory");
    asm volatile("barrier.cluster.wait.aligned;"   ::: "memory");
}

// ============================================================
extern "C" void kernel_launch(void* const* d_in, const int* in_sizes, int n_in,
                              void* d_out, int out_size)
{
    (void)in_sizes; (void)n_in; (void)out_size;
    const float* x    = (const float*)d_in[0];
    const float* Wx   = (const float*)d_in[1];
    const float* Wh   = (const float*)d_in[2];
    const float* bias = (const float*)d_in[3];
    float* out = (float*)d_out;

    cudaFuncSetAttribute(rnn_scan, cudaFuncAttributeMaxDynamicSharedMemorySize, SMEM_SCAN2);

    dim3 g1(4, 1024);
    xp_gemm<<<g1, 256>>>(x, Wx, bias);
    rnn_scan<<<128, 512, SMEM_SCAN2>>>(Wh, out);
}